// round 3
// baseline (speedup 1.0000x reference)
#include <cuda_runtime.h>
#include <cuda_bf16.h>
#include <cstdint>
#include <math.h>

// Problem dims (fixed by the dataset)
#define BATCH 16
#define SEQ   512
#define MROWS (BATCH * SEQ)      // 8192
#define KDIM  9984
#define H1    1000
#define H2    40
#define NKT   (KDIM / 32)        // 312 K-tiles

// -------- scratch (device globals; no allocation allowed) --------
__device__ float g_h1[MROWS * H1];       // relu(X@W1+b1)
__device__ float g_logits[MROWS];        // sigmoid output per (b,s)
__device__ int   g_ts_is_i32;            // 1 if token_starts is int32, 0 if int64

// ============================================================================
// GEMM1: g_h1 = relu(X[8192,9984] @ W1[9984,1000] + b1)  -- tf32 mma.sync
// Tiling: BM=128, BN=128, BK=32, 256 threads (8 warps as 4x2), warp tile 32x64
// ============================================================================

__device__ __forceinline__ uint32_t f2tf32(float x) {
    uint32_t u;
    asm("cvt.rna.tf32.f32 %0, %1;" : "=r"(u) : "f"(x));
    return u;
}

__device__ __forceinline__ void cp16(float* dst_smem, const float* src, bool pred) {
    uint32_t d = (uint32_t)__cvta_generic_to_shared(dst_smem);
    int sz = pred ? 16 : 0;
    asm volatile("cp.async.cg.shared.global [%0], [%1], 16, %2;\n"
                 :: "r"(d), "l"(src), "r"(sz));
}

// shared layout (floats): As[2][128][36] then Bs[2][32][136]
#define AS_STRIDE 36
#define BS_STRIDE 136
#define AS_BUF (128 * AS_STRIDE)     // 4608
#define BS_BUF (32 * BS_STRIDE)      // 4352
#define SMEM_FLOATS (2 * AS_BUF + 2 * BS_BUF)   // 17920 floats = 71680 B

__global__ void gemm1_tf32_kernel(const float* __restrict__ X,
                                  const float* __restrict__ W1,
                                  const float* __restrict__ b1) {
    extern __shared__ float smem[];
    float* As = smem;                 // 2 buffers
    float* Bs = smem + 2 * AS_BUF;    // 2 buffers

    const int tid = threadIdx.x;
    const int warp = tid >> 5;
    const int lane = tid & 31;
    const int grp = lane >> 2;     // 0..7
    const int qid = lane & 3;      // 0..3
    const int warp_m = warp & 3;   // 0..3 -> 32 rows each
    const int warp_n = warp >> 2;  // 0..1 -> 64 cols each

    const int m0 = blockIdx.y * 128;
    const int n0 = blockIdx.x * 128;

    float acc[2][8][4];
#pragma unroll
    for (int im = 0; im < 2; im++)
#pragma unroll
        for (int in = 0; in < 8; in++)
#pragma unroll
            for (int r = 0; r < 4; r++) acc[im][in][r] = 0.0f;

    // ---- stage loader ----
    auto load_stage = [&](int kt, int buf) {
        float* Ad = As + buf * AS_BUF;
        float* Bd = Bs + buf * BS_BUF;
        // A: 128 rows x 8 float4
#pragma unroll
        for (int i = 0; i < 4; i++) {
            int idx = tid + 256 * i;
            int r = idx >> 3, kq = idx & 7;
            const float* src = X + (long)(m0 + r) * KDIM + kt * 32 + kq * 4;
            cp16(Ad + r * AS_STRIDE + kq * 4, src, true);
        }
        // B: 32 rows x 32 float4 (guard cols >= 1000 -> zero-fill)
#pragma unroll
        for (int i = 0; i < 4; i++) {
            int idx = tid + 256 * i;
            int kr = idx >> 5, nq = idx & 31;
            int col = n0 + nq * 4;
            bool ok = (col < H1);
            const float* src = W1 + (long)(kt * 32 + kr) * H1 + (ok ? col : 0);
            cp16(Bd + kr * BS_STRIDE + nq * 4, src, ok);
        }
    };

    load_stage(0, 0);
    asm volatile("cp.async.commit_group;\n" ::);

    for (int kt = 0; kt < NKT; kt++) {
        int buf = kt & 1;
        if (kt + 1 < NKT) {
            load_stage(kt + 1, buf ^ 1);
            asm volatile("cp.async.commit_group;\n" ::);
            asm volatile("cp.async.wait_group 1;\n" ::);
        } else {
            asm volatile("cp.async.wait_group 0;\n" ::);
        }
        __syncthreads();

        const float* Ab = As + buf * AS_BUF;
        const float* Bb = Bs + buf * BS_BUF;

#pragma unroll
        for (int ks = 0; ks < 4; ks++) {
            uint32_t af[2][4];
#pragma unroll
            for (int im = 0; im < 2; im++) {
                const float* ap = Ab + (warp_m * 32 + im * 16 + grp) * AS_STRIDE + ks * 8 + qid;
                af[im][0] = f2tf32(ap[0]);
                af[im][1] = f2tf32(ap[8 * AS_STRIDE]);
                af[im][2] = f2tf32(ap[4]);
                af[im][3] = f2tf32(ap[8 * AS_STRIDE + 4]);
            }
#pragma unroll
            for (int in = 0; in < 8; in++) {
                const float* bp = Bb + (ks * 8 + qid) * BS_STRIDE + warp_n * 64 + in * 8 + grp;
                uint32_t b0 = f2tf32(bp[0]);
                uint32_t b1r = f2tf32(bp[4 * BS_STRIDE]);
#pragma unroll
                for (int im = 0; im < 2; im++) {
                    asm volatile(
                        "mma.sync.aligned.m16n8k8.row.col.f32.tf32.tf32.f32 "
                        "{%0,%1,%2,%3}, {%4,%5,%6,%7}, {%8,%9}, {%0,%1,%2,%3};\n"
                        : "+f"(acc[im][in][0]), "+f"(acc[im][in][1]),
                          "+f"(acc[im][in][2]), "+f"(acc[im][in][3])
                        : "r"(af[im][0]), "r"(af[im][1]), "r"(af[im][2]), "r"(af[im][3]),
                          "r"(b0), "r"(b1r));
                }
            }
        }
        __syncthreads();
    }

    // ---- epilogue: bias + relu + store ----
#pragma unroll
    for (int im = 0; im < 2; im++) {
#pragma unroll
        for (int in = 0; in < 8; in++) {
            int row = m0 + warp_m * 32 + im * 16 + grp;
            int col = n0 + warp_n * 64 + in * 8 + qid * 2;
            if (col < H1) {
                float bb0 = b1[col], bb1 = b1[col + 1];
                float2 v0, v1;
                v0.x = fmaxf(acc[im][in][0] + bb0, 0.0f);
                v0.y = fmaxf(acc[im][in][1] + bb1, 0.0f);
                v1.x = fmaxf(acc[im][in][2] + bb0, 0.0f);
                v1.y = fmaxf(acc[im][in][3] + bb1, 0.0f);
                *(float2*)(g_h1 + (long)row * H1 + col) = v0;
                *(float2*)(g_h1 + (long)(row + 8) * H1 + col) = v1;
            }
        }
    }
}

// ============================================================================
// GEMM2+GEMM3+sigmoid fused: per-row 40-wide hidden, then dot with W3, sigmoid
// 64 threads per block, one row per thread, 128 blocks.
// ============================================================================
__global__ void head_kernel(const float* __restrict__ W2,
                            const float* __restrict__ b2,
                            const float* __restrict__ W3,
                            const float* __restrict__ b3) {
    __shared__ float hs[64][41];       // 64 rows x 40 k-chunk (padded)
    __shared__ float w2s[40 * 40];     // k-chunk x 40 cols

    const int tid = threadIdx.x;       // 0..63
    const int row0 = blockIdx.x * 64;
    const int row = row0 + tid;

    float acc[H2];
#pragma unroll
    for (int c = 0; c < H2; c++) acc[c] = 0.0f;

    for (int kc = 0; kc < 25; kc++) {          // 25 chunks of 40 -> K=1000
        // load h1 chunk (coalesced-ish)
#pragma unroll 8
        for (int i = 0; i < 40; i++) {
            int idx = tid + 64 * i;            // 0..2559
            int r = idx / 40, k = idx - r * 40;
            hs[r][k] = g_h1[(long)(row0 + r) * H1 + kc * 40 + k];
        }
        // load W2 chunk (contiguous 1600 floats)
#pragma unroll
        for (int i = 0; i < 25; i++) {
            int idx = tid + 64 * i;
            w2s[idx] = W2[kc * 40 * H2 + idx];
        }
        __syncthreads();
#pragma unroll 4
        for (int k = 0; k < 40; k++) {
            float a = hs[tid][k];
            const float4* wrow = (const float4*)(w2s + k * H2);
#pragma unroll
            for (int c4 = 0; c4 < 10; c4++) {
                float4 w = wrow[c4];
                acc[c4 * 4 + 0] += a * w.x;
                acc[c4 * 4 + 1] += a * w.y;
                acc[c4 * 4 + 2] += a * w.z;
                acc[c4 * 4 + 3] += a * w.w;
            }
        }
        __syncthreads();
    }

    float logit = b3[0];
#pragma unroll
    for (int c = 0; c < H2; c++) {
        float h = fmaxf(acc[c] + b2[c], 0.0f);
        logit += h * W3[c];
    }
    g_logits[row] = 1.0f / (1.0f + expf(-logit));
}

// ============================================================================
// token_starts dtype detection: values are in [0,512). If stored as int64 (LE),
// every odd 32-bit word among the first 8192 words is a zero high-half.
// If int32, odd words are actual sorted indices (essentially never all zero).
// ============================================================================
__global__ void detect_kernel(const unsigned int* __restrict__ w) {
    __shared__ int s;
    if (threadIdx.x == 0) s = 0;
    __syncthreads();
    int loc = 0;
    for (int i = threadIdx.x; i < 4096; i += 256)
        if (w[2 * i + 1] != 0u) loc = 1;
    if (loc) s = 1;
    __syncthreads();
    if (threadIdx.x == 0) g_ts_is_i32 = s;
}

__global__ void gather_kernel(const void* __restrict__ tsp,
                              float* __restrict__ out) {
    int i = blockIdx.x * blockDim.x + threadIdx.x;
    if (i >= MROWS) return;
    long long ts;
    if (g_ts_is_i32) ts = ((const int*)tsp)[i];
    else             ts = ((const long long*)tsp)[i];
    int b = i >> 9;
    out[i] = (ts != 0) ? g_logits[(b << 9) + (int)ts] : 0.0f;
}

// ============================================================================
// launch
// ============================================================================
extern "C" void kernel_launch(void* const* d_in, const int* in_sizes, int n_in,
                              void* d_out, int out_size) {
    const float* X   = (const float*)d_in[0];
    const void*  tsp = d_in[1];
    const float* W1  = (const float*)d_in[2];
    const float* b1  = (const float*)d_in[3];
    const float* W2  = (const float*)d_in[4];
    const float* b2  = (const float*)d_in[5];
    const float* W3  = (const float*)d_in[6];
    const float* b3  = (const float*)d_in[7];
    float* out = (float*)d_out;

    (void)in_sizes; (void)n_in; (void)out_size;

    cudaFuncSetAttribute(gemm1_tf32_kernel,
                         cudaFuncAttributeMaxDynamicSharedMemorySize,
                         SMEM_FLOATS * (int)sizeof(float));

    detect_kernel<<<1, 256>>>((const unsigned int*)tsp);

    dim3 grid1(8, 64);   // x: 8 n-tiles (128 cols), y: 64 m-tiles (128 rows)
    gemm1_tf32_kernel<<<grid1, 256, SMEM_FLOATS * sizeof(float)>>>(X, W1, b1);

    head_kernel<<<128, 64>>>(W2, b2, W3, b3);

    gather_kernel<<<32, 256>>>(tsp, out);
}

// round 7
// speedup vs baseline: 1.9593x; 1.9593x over previous
#include <cuda_runtime.h>
#include <cuda_bf16.h>
#include <cstdint>
#include <math.h>

// ---------------- problem dims ----------------
#define MROWS 8192
#define KDIM  9984
#define H1    1000
#define H1P   1024
#define H2    40

// ---------------- GEMM1 tiling ----------------
#define BM 128
#define BN 256
#define BK 32
#define STAGES 4
#define NKT (KDIM / BK)          // 312
#define A_STRIDE 40              // bf16 elems per smem row (80 B) -> conflict-free ldmatrix
#define B_STRIDE 40
#define A_TILE_B (BM * A_STRIDE * 2)          // 10240
#define B_TILE_B (BN * B_STRIDE * 2)          // 20480
#define STAGE_B  (A_TILE_B + B_TILE_B)        // 30720
#define SMEM_B   (STAGES * STAGE_B)           // 122880

// ---------------- scratch (device globals; no runtime alloc) ----------------
__device__ __nv_bfloat16 g_Xbf[(size_t)MROWS * KDIM];   // 163.6 MB
__device__ __nv_bfloat16 g_W1t[(size_t)H1P * KDIM];     // 20.4 MB, [n][k], rows >= 1000 zero
__device__ float g_h1[(size_t)MROWS * H1];              // 32.7 MB
__device__ float g_part[5][MROWS * H2];                 // head k-split partials
__device__ float g_logits[MROWS];
__device__ int   g_ts_is_i32;

// ============================================================================
// helpers
// ============================================================================
__device__ __forceinline__ uint32_t smem_u32(const void* p) {
    uint32_t a;
    asm("{ .reg .u64 t; cvta.to.shared.u64 t, %1; cvt.u32.u64 %0, t; }"
        : "=r"(a) : "l"(p));
    return a;
}

__device__ __forceinline__ void cpa16(uint32_t dst, const void* src) {
    asm volatile("cp.async.cg.shared.global [%0], [%1], 16;\n" :: "r"(dst), "l"(src));
}

__device__ __forceinline__ void ldsm4(uint32_t& r0, uint32_t& r1, uint32_t& r2,
                                      uint32_t& r3, uint32_t addr) {
    asm volatile("ldmatrix.sync.aligned.m8n8.x4.shared.b16 {%0,%1,%2,%3}, [%4];"
                 : "=r"(r0), "=r"(r1), "=r"(r2), "=r"(r3) : "r"(addr));
}

__device__ __forceinline__ void mma_bf16(float* d, const uint32_t* a, const uint32_t* b) {
    asm volatile(
        "mma.sync.aligned.m16n8k16.row.col.f32.bf16.bf16.f32 "
        "{%0,%1,%2,%3}, {%4,%5,%6,%7}, {%8,%9}, {%0,%1,%2,%3};\n"
        : "+f"(d[0]), "+f"(d[1]), "+f"(d[2]), "+f"(d[3])
        : "r"(a[0]), "r"(a[1]), "r"(a[2]), "r"(a[3]), "r"(b[0]), "r"(b[1]));
}

// ============================================================================
// pre-pass 1: X fp32 -> bf16
// ============================================================================
__global__ void convert_x_kernel(const float* __restrict__ X) {
    size_t n4 = (size_t)MROWS * KDIM / 4;
    size_t stride = (size_t)gridDim.x * blockDim.x;
    for (size_t i = (size_t)blockIdx.x * blockDim.x + threadIdx.x; i < n4; i += stride) {
        float4 v = ((const float4*)X)[i];
        __nv_bfloat162 lo = __floats2bfloat162_rn(v.x, v.y);
        __nv_bfloat162 hi = __floats2bfloat162_rn(v.z, v.w);
        uint2 pk;
        pk.x = *(uint32_t*)&lo;
        pk.y = *(uint32_t*)&hi;
        ((uint2*)g_Xbf)[i] = pk;
    }
}

// ============================================================================
// pre-pass 2: W1[K][H1] fp32 -> g_W1t[H1P][K] bf16 (transpose + pad)
// ============================================================================
__global__ void convert_w1_kernel(const float* __restrict__ W1) {
    __shared__ float t[32][33];
    int k0 = blockIdx.x * 32, n0 = blockIdx.y * 32;
#pragma unroll
    for (int yy = 0; yy < 32; yy += 8) {
        int k = k0 + threadIdx.y + yy, n = n0 + threadIdx.x;
        t[threadIdx.y + yy][threadIdx.x] = (n < H1) ? W1[(size_t)k * H1 + n] : 0.0f;
    }
    __syncthreads();
#pragma unroll
    for (int yy = 0; yy < 32; yy += 8) {
        int n = n0 + threadIdx.y + yy, k = k0 + threadIdx.x;
        g_W1t[(size_t)n * KDIM + k] = __float2bfloat16(t[threadIdx.x][threadIdx.y + yy]);
    }
}

// ============================================================================
// GEMM1: g_h1 = relu(Xbf[8192,9984] @ W1t^T + b1)
// bf16 mma.sync m16n8k16, 256 threads, 8 warps (2 m x 4 n), 4-stage cp.async
// grid (H1P/BN = 4, MROWS/BM = 64)
// ============================================================================
__global__ void __launch_bounds__(256, 1)
gemm1_kernel(const float* __restrict__ b1) {
    extern __shared__ __align__(128) char smem[];
    const uint32_t sb = smem_u32(smem);

    const int tid = threadIdx.x;
    const int warp = tid >> 5;
    const int lane = tid & 31;
    const int warp_m = warp & 1;     // 0..1, 64 rows each
    const int warp_n = warp >> 1;    // 0..3, 64 cols each
    const int m0 = blockIdx.y * BM;
    const int n0 = blockIdx.x * BN;

    float acc[4][8][4];
#pragma unroll
    for (int i = 0; i < 4; i++)
#pragma unroll
        for (int j = 0; j < 8; j++)
#pragma unroll
            for (int r = 0; r < 4; r++) acc[i][j][r] = 0.0f;

    // ---- stage loader: A 512 chunks (2/thr), B 1024 chunks (4/thr) ----
    const int lr = tid >> 2;          // 0..63
    const int lc = tid & 3;           // 0..3
    const __nv_bfloat16* Abase = g_Xbf + (size_t)m0 * KDIM;
    const __nv_bfloat16* Bbase = g_W1t + (size_t)n0 * KDIM;

    auto load_stage = [&](int kt, int stage) {
        uint32_t as = sb + stage * STAGE_B;
        uint32_t bs = as + A_TILE_B;
        const __nv_bfloat16* asrc = Abase + (size_t)kt * BK + lc * 8;
        const __nv_bfloat16* bsrc = Bbase + (size_t)kt * BK + lc * 8;
#pragma unroll
        for (int i = 0; i < 2; i++) {
            int r = lr + 64 * i;
            cpa16(as + r * (A_STRIDE * 2) + lc * 16, asrc + (size_t)r * KDIM);
        }
#pragma unroll
        for (int i = 0; i < 4; i++) {
            int r = lr + 64 * i;
            cpa16(bs + r * (B_STRIDE * 2) + lc * 16, bsrc + (size_t)r * KDIM);
        }
    };

#pragma unroll
    for (int s = 0; s < STAGES - 1; s++) {
        load_stage(s, s);
        asm volatile("cp.async.commit_group;\n" ::);
    }

    // precomputed fragment addresses (lane-dependent parts)
    const uint32_t a_lane_row = (uint32_t)(lane & 15);
    const uint32_t a_lane_k   = (uint32_t)((lane >> 4) * 16);
    const int bj = lane >> 3;                       // 0..3
    const uint32_t b_lane_row = (uint32_t)((bj >> 1) * 8 + (lane & 7));
    const uint32_t b_lane_k   = (uint32_t)((bj & 1) * 16);

    for (int kt = 0; kt < NKT; kt++) {
        asm volatile("cp.async.wait_group %0;\n" :: "n"(STAGES - 2));
        __syncthreads();

        if (kt + STAGES - 1 < NKT)
            load_stage(kt + STAGES - 1, (kt + STAGES - 1) & (STAGES - 1));
        asm volatile("cp.async.commit_group;\n" ::);

        const int st = kt & (STAGES - 1);
        const uint32_t as = sb + st * STAGE_B;
        const uint32_t bs = as + A_TILE_B;

#pragma unroll
        for (int ks = 0; ks < 2; ks++) {
            uint32_t af[4][4];
#pragma unroll
            for (int ms = 0; ms < 4; ms++) {
                uint32_t row = (uint32_t)(warp_m * 64 + ms * 16) + a_lane_row;
                ldsm4(af[ms][0], af[ms][1], af[ms][2], af[ms][3],
                      as + row * (A_STRIDE * 2) + ks * 32 + a_lane_k);
            }
            uint32_t bf[8][2];
#pragma unroll
            for (int np = 0; np < 4; np++) {
                uint32_t row = (uint32_t)(warp_n * 64 + np * 16) + b_lane_row;
                ldsm4(bf[2 * np][0], bf[2 * np][1], bf[2 * np + 1][0], bf[2 * np + 1][1],
                      bs + row * (B_STRIDE * 2) + ks * 32 + b_lane_k);
            }
#pragma unroll
            for (int ms = 0; ms < 4; ms++)
#pragma unroll
                for (int nf = 0; nf < 8; nf++)
                    mma_bf16(acc[ms][nf], af[ms], bf[nf]);
        }
        __syncthreads();
    }

    // ---- epilogue: bias + relu ----
    const int erow = (lane >> 2);
    const int ecol = (lane & 3) * 2;
#pragma unroll
    for (int ms = 0; ms < 4; ms++) {
        int r0 = m0 + warp_m * 64 + ms * 16 + erow;
#pragma unroll
        for (int nf = 0; nf < 8; nf++) {
            int col = n0 + warp_n * 64 + nf * 8 + ecol;
            if (col < H1) {
                float2 bb = *(const float2*)(b1 + col);
                float2 v0, v1;
                v0.x = fmaxf(acc[ms][nf][0] + bb.x, 0.0f);
                v0.y = fmaxf(acc[ms][nf][1] + bb.y, 0.0f);
                v1.x = fmaxf(acc[ms][nf][2] + bb.x, 0.0f);
                v1.y = fmaxf(acc[ms][nf][3] + bb.y, 0.0f);
                *(float2*)(g_h1 + (size_t)r0 * H1 + col) = v0;
                *(float2*)(g_h1 + (size_t)(r0 + 8) * H1 + col) = v1;
            }
        }
    }
}

// ============================================================================
// head partial: GEMM2 k-split (5 splits of 200) -> g_part[ks][row][40]
// grid (64, 5), block 128 (1 row/thread)
// ============================================================================
__global__ void head_partial_kernel(const float* __restrict__ W2) {
    __shared__ float hs[128][41];
    __shared__ float w2s[40 * 40];
    const int tid = threadIdx.x;
    const int row0 = blockIdx.x * 128;
    const int kc0 = blockIdx.y * 5;

    float acc[H2];
#pragma unroll
    for (int c = 0; c < H2; c++) acc[c] = 0.0f;

    for (int kc = kc0; kc < kc0 + 5; kc++) {
#pragma unroll 8
        for (int i = 0; i < 40; i++) {
            int idx = tid + 128 * i;
            int r = idx / 40, k = idx - r * 40;
            hs[r][k] = g_h1[(size_t)(row0 + r) * H1 + kc * 40 + k];
        }
#pragma unroll
        for (int i = 0; i < 13; i++) {
            int idx = tid + 128 * i;
            if (idx < 1600) w2s[idx] = W2[kc * 40 * H2 + idx];
        }
        __syncthreads();
#pragma unroll 5
        for (int k = 0; k < 40; k++) {
            float a = hs[tid][k];
            const float4* wr = (const float4*)(w2s + k * H2);
#pragma unroll
            for (int c4 = 0; c4 < 10; c4++) {
                float4 w = wr[c4];
                acc[c4 * 4 + 0] += a * w.x;
                acc[c4 * 4 + 1] += a * w.y;
                acc[c4 * 4 + 2] += a * w.z;
                acc[c4 * 4 + 3] += a * w.w;
            }
        }
        __syncthreads();
    }
    float4* dst = (float4*)&g_part[blockIdx.y][(row0 + tid) * H2];
#pragma unroll
    for (int c4 = 0; c4 < 10; c4++)
        dst[c4] = make_float4(acc[c4 * 4], acc[c4 * 4 + 1], acc[c4 * 4 + 2], acc[c4 * 4 + 3]);
}

// combine partials + bias + relu + W3 dot + sigmoid
__global__ void head_combine_kernel(const float* __restrict__ b2,
                                    const float* __restrict__ W3,
                                    const float* __restrict__ b3) {
    int row = blockIdx.x * blockDim.x + threadIdx.x;
    if (row >= MROWS) return;
    float4 a[10];
    const float4* p0 = (const float4*)&g_part[0][row * H2];
#pragma unroll
    for (int i = 0; i < 10; i++) a[i] = p0[i];
#pragma unroll
    for (int p = 1; p < 5; p++) {
        const float4* pp = (const float4*)&g_part[p][row * H2];
#pragma unroll
        for (int i = 0; i < 10; i++) {
            float4 v = pp[i];
            a[i].x += v.x; a[i].y += v.y; a[i].z += v.z; a[i].w += v.w;
        }
    }
    float logit = b3[0];
#pragma unroll
    for (int i = 0; i < 10; i++) {
        float4 bb = *(const float4*)(b2 + i * 4);
        float4 ww = *(const float4*)(W3 + i * 4);
        logit += fmaxf(a[i].x + bb.x, 0.0f) * ww.x;
        logit += fmaxf(a[i].y + bb.y, 0.0f) * ww.y;
        logit += fmaxf(a[i].z + bb.z, 0.0f) * ww.z;
        logit += fmaxf(a[i].w + bb.w, 0.0f) * ww.w;
    }
    g_logits[row] = 1.0f / (1.0f + expf(-logit));
}

// ============================================================================
// token_starts dtype detect + masked gather
// ============================================================================
__global__ void detect_kernel(const unsigned int* __restrict__ w) {
    __shared__ int s;
    if (threadIdx.x == 0) s = 0;
    __syncthreads();
    int loc = 0;
    for (int i = threadIdx.x; i < 4096; i += 256)
        if (w[2 * i + 1] != 0u) loc = 1;
    if (loc) s = 1;
    __syncthreads();
    if (threadIdx.x == 0) g_ts_is_i32 = s;
}

__global__ void gather_kernel(const void* __restrict__ tsp, float* __restrict__ out) {
    int i = blockIdx.x * blockDim.x + threadIdx.x;
    if (i >= MROWS) return;
    long long ts;
    if (g_ts_is_i32) ts = ((const int*)tsp)[i];
    else             ts = ((const long long*)tsp)[i];
    int b = i >> 9;
    out[i] = (ts != 0) ? g_logits[(b << 9) + (int)ts] : 0.0f;
}

// ============================================================================
// launch
// ============================================================================
extern "C" void kernel_launch(void* const* d_in, const int* in_sizes, int n_in,
                              void* d_out, int out_size) {
    const float* X   = (const float*)d_in[0];
    const void*  tsp = d_in[1];
    const float* W1  = (const float*)d_in[2];
    const float* b1  = (const float*)d_in[3];
    const float* W2  = (const float*)d_in[4];
    const float* b2  = (const float*)d_in[5];
    const float* W3  = (const float*)d_in[6];
    const float* b3  = (const float*)d_in[7];
    float* out = (float*)d_out;
    (void)in_sizes; (void)n_in; (void)out_size;

    cudaFuncSetAttribute(gemm1_kernel,
                         cudaFuncAttributeMaxDynamicSharedMemorySize, SMEM_B);

    convert_x_kernel<<<2048, 256>>>(X);
    convert_w1_kernel<<<dim3(KDIM / 32, H1P / 32), dim3(32, 8)>>>(W1);
    detect_kernel<<<1, 256>>>((const unsigned int*)tsp);

    gemm1_kernel<<<dim3(H1P / BN, MROWS / BM), 256, SMEM_B>>>(b1);

    head_partial_kernel<<<dim3(64, 5), 128>>>(W2);
    head_combine_kernel<<<32, 256>>>(b2, W3, b3);
    gather_kernel<<<32, 256>>>(tsp, out);
}

// round 9
// speedup vs baseline: 2.9239x; 1.4923x over previous
#include <cuda_runtime.h>
#include <cuda_bf16.h>
#include <cstdint>
#include <math.h>

// ---------------- problem dims ----------------
#define MROWS 8192
#define KDIM  9984
#define H1    1000
#define H1P   1024
#define H2    40

// ---------------- GEMM1 tiling ----------------
#define BM 128
#define BN 128
#define BK 32
#define STAGES 4
#define NKT (KDIM / BK)          // 312
#define RSTRIDE 40               // bf16 elems per smem row (80 B) -> conflict-free ldmatrix
#define A_TILE_B (BM * RSTRIDE * 2)          // 10240
#define STAGE_B  ((BM + BN) * RSTRIDE * 2)   // 20480
#define SMEM_B   (STAGES * STAGE_B)          // 81920

// ---------------- scratch (device globals; no runtime alloc) ----------------
__device__ __nv_bfloat16 g_Xbf[(size_t)MROWS * KDIM];   // compact bf16 X rows
__device__ __nv_bfloat16 g_W1t[(size_t)H1P * KDIM];     // [n][k], rows >= 1000 zero
__device__ float g_h1[(size_t)MROWS * H1];              // compact
__device__ float g_part[5][MROWS * H2];
__device__ float g_logits[MROWS];                       // compact
__device__ int   g_ts_is_i32;
__device__ unsigned char g_mark[MROWS];
__device__ int   g_cidx[MROWS];                         // (b,s) -> compact row
__device__ int   g_list[MROWS];                         // compact row -> original row
__device__ int   g_count, g_mtiles, g_ntiles, g_tile_ctr;

// ============================================================================
// helpers
// ============================================================================
__device__ __forceinline__ uint32_t smem_u32(const void* p) {
    uint32_t a;
    asm("{ .reg .u64 t; cvta.to.shared.u64 t, %1; cvt.u32.u64 %0, t; }"
        : "=r"(a) : "l"(p));
    return a;
}
__device__ __forceinline__ void cpa16(uint32_t dst, const void* src) {
    asm volatile("cp.async.cg.shared.global [%0], [%1], 16;\n" :: "r"(dst), "l"(src));
}
__device__ __forceinline__ void ldsm4(uint32_t& r0, uint32_t& r1, uint32_t& r2,
                                      uint32_t& r3, uint32_t addr) {
    asm volatile("ldmatrix.sync.aligned.m8n8.x4.shared.b16 {%0,%1,%2,%3}, [%4];"
                 : "=r"(r0), "=r"(r1), "=r"(r2), "=r"(r3) : "r"(addr));
}
__device__ __forceinline__ void mma_bf16(float* d, const uint32_t* a, const uint32_t* b) {
    asm volatile(
        "mma.sync.aligned.m16n8k16.row.col.f32.bf16.bf16.f32 "
        "{%0,%1,%2,%3}, {%4,%5,%6,%7}, {%8,%9}, {%0,%1,%2,%3};\n"
        : "+f"(d[0]), "+f"(d[1]), "+f"(d[2]), "+f"(d[3])
        : "r"(a[0]), "r"(a[1]), "r"(a[2]), "r"(a[3]), "r"(b[0]), "r"(b[1]));
}

// ============================================================================
// token_starts dtype detect + mark/scan compaction
// ============================================================================
__global__ void detect_kernel(const unsigned int* __restrict__ w) {
    __shared__ int s;
    if (threadIdx.x == 0) s = 0;
    __syncthreads();
    int loc = 0;
    for (int i = threadIdx.x; i < 4096; i += 256)
        if (w[2 * i + 1] != 0u) loc = 1;
    if (loc) s = 1;
    __syncthreads();
    if (threadIdx.x == 0) g_ts_is_i32 = s;
}

__global__ void zero_mark_kernel() {
    ((unsigned long long*)g_mark)[threadIdx.x] = 0ULL;   // 1024 thr x 8B = 8192
}

__global__ void scatter_mark_kernel(const void* __restrict__ tsp) {
    int i = blockIdx.x * 1024 + threadIdx.x;             // grid 8
    long long ts = g_ts_is_i32 ? (long long)((const int*)tsp)[i]
                               : ((const long long*)tsp)[i];
    if (ts != 0) g_mark[((i >> 9) << 9) + (int)ts] = 1;
}

__global__ void scan_kernel() {
    __shared__ int wsum[32];
    const int tid = threadIdx.x, lane = tid & 31, wid = tid >> 5;
    const int base = tid * 8;
    int loc[8], s = 0;
#pragma unroll
    for (int j = 0; j < 8; j++) { loc[j] = s; s += g_mark[base + j]; }
    int v = s;
#pragma unroll
    for (int o = 1; o < 32; o <<= 1) {
        int u = __shfl_up_sync(0xffffffffu, v, o);
        if (lane >= o) v += u;
    }
    if (lane == 31) wsum[wid] = v;
    __syncthreads();
    if (wid == 0) {
        int w = wsum[lane];
#pragma unroll
        for (int o = 1; o < 32; o <<= 1) {
            int u = __shfl_up_sync(0xffffffffu, w, o);
            if (lane >= o) w += u;
        }
        wsum[lane] = w;
    }
    __syncthreads();
    int tb = (wid > 0 ? wsum[wid - 1] : 0) + (v - s);
#pragma unroll
    for (int j = 0; j < 8; j++) {
        if (g_mark[base + j]) {
            int c = tb + loc[j];
            g_cidx[base + j] = c;
            g_list[c] = base + j;
        }
    }
    int total = wsum[31];
    int mt = (total + 127) >> 7;
    if (tid == 0) {
        g_count = total;
        g_mtiles = mt;
        g_ntiles = mt * (H1P / BN);
        g_tile_ctr = 0;
    }
    for (int i = total + tid; i < mt * 128; i += 1024) g_list[i] = 0;  // pad
}

// ============================================================================
// pre-pass: convert only needed X rows fp32 -> bf16 (compact layout)
// ============================================================================
__global__ void convert_x_rows_kernel(const float* __restrict__ X) {
    const int padded = g_mtiles * 128;
    for (int r = blockIdx.x; r < padded; r += gridDim.x) {
        int row = g_list[r];
        const float4* src = (const float4*)(X + (size_t)row * KDIM);
        uint4* dst = (uint4*)(g_Xbf + (size_t)r * KDIM);
        for (int c = threadIdx.x; c < KDIM / 8; c += blockDim.x) {
            float4 v0 = src[2 * c], v1 = src[2 * c + 1];
            __nv_bfloat162 p0 = __floats2bfloat162_rn(v0.x, v0.y);
            __nv_bfloat162 p1 = __floats2bfloat162_rn(v0.z, v0.w);
            __nv_bfloat162 p2 = __floats2bfloat162_rn(v1.x, v1.y);
            __nv_bfloat162 p3 = __floats2bfloat162_rn(v1.z, v1.w);
            uint4 o;
            o.x = *(uint32_t*)&p0; o.y = *(uint32_t*)&p1;
            o.z = *(uint32_t*)&p2; o.w = *(uint32_t*)&p3;
            dst[c] = o;
        }
    }
}

// W1[K][H1] fp32 -> g_W1t[H1P][K] bf16 (transpose + pad)
__global__ void convert_w1_kernel(const float* __restrict__ W1) {
    __shared__ float t[32][33];
    int k0 = blockIdx.x * 32, n0 = blockIdx.y * 32;
#pragma unroll
    for (int yy = 0; yy < 32; yy += 8) {
        int k = k0 + threadIdx.y + yy, n = n0 + threadIdx.x;
        t[threadIdx.y + yy][threadIdx.x] = (n < H1) ? W1[(size_t)k * H1 + n] : 0.0f;
    }
    __syncthreads();
#pragma unroll
    for (int yy = 0; yy < 32; yy += 8) {
        int n = n0 + threadIdx.y + yy, k = k0 + threadIdx.x;
        g_W1t[(size_t)n * KDIM + k] = __float2bfloat16(t[threadIdx.x][threadIdx.y + yy]);
    }
}

// ============================================================================
// GEMM1 (persistent, work-stealing): g_h1 = relu(Xbf_compact @ W1t^T + b1)
// BM=128 BN=128 BK=32, 8 warps (2m x 4n), warp tile 64x32, 2 CTAs/SM
// ============================================================================
__global__ void __launch_bounds__(256, 2)
gemm1_kernel(const float* __restrict__ b1) {
    extern __shared__ __align__(128) char smem[];
    const uint32_t sb = smem_u32(smem);
    __shared__ int s_t;

    const int tid = threadIdx.x;
    const int warp = tid >> 5;
    const int lane = tid & 31;
    const int warp_m = warp & 1;     // 0..1, 64 rows
    const int warp_n = warp >> 1;    // 0..3, 32 cols
    const int ntiles = g_ntiles;

    const int lr = tid >> 2;         // 0..63
    const int lc = tid & 3;          // 0..3
    const uint32_t a_lane_row = (uint32_t)(lane & 15);
    const uint32_t a_lane_k   = (uint32_t)((lane >> 4) * 16);
    const int bj = lane >> 3;
    const uint32_t b_lane_row = (uint32_t)((bj >> 1) * 8 + (lane & 7));
    const uint32_t b_lane_k   = (uint32_t)((bj & 1) * 16);
    const int erow = lane >> 2;
    const int ecol = (lane & 3) * 2;

    while (true) {
        if (tid == 0) s_t = atomicAdd(&g_tile_ctr, 1);
        __syncthreads();
        const int t = s_t;
        if (t >= ntiles) break;
        const int m0 = (t >> 3) * BM;      // H1P/BN = 8 n-tiles
        const int n0 = (t & 7) * BN;

        const __nv_bfloat16* Abase = g_Xbf + (size_t)m0 * KDIM;
        const __nv_bfloat16* Bbase = g_W1t + (size_t)n0 * KDIM;

        float acc[4][4][4];
#pragma unroll
        for (int i = 0; i < 4; i++)
#pragma unroll
            for (int j = 0; j < 4; j++)
#pragma unroll
                for (int r = 0; r < 4; r++) acc[i][j][r] = 0.0f;

        auto load_stage = [&](int kt, int stage) {
            uint32_t as = sb + stage * STAGE_B;
            uint32_t bs = as + A_TILE_B;
            const __nv_bfloat16* asrc = Abase + (size_t)kt * BK + lc * 8;
            const __nv_bfloat16* bsrc = Bbase + (size_t)kt * BK + lc * 8;
#pragma unroll
            for (int i = 0; i < 2; i++) {
                int r = lr + 64 * i;
                cpa16(as + r * (RSTRIDE * 2) + lc * 16, asrc + (size_t)r * KDIM);
                cpa16(bs + r * (RSTRIDE * 2) + lc * 16, bsrc + (size_t)r * KDIM);
            }
        };

#pragma unroll
        for (int s = 0; s < STAGES - 1; s++) {
            load_stage(s, s);
            asm volatile("cp.async.commit_group;\n" ::);
        }

        for (int kt = 0; kt < NKT; kt++) {
            asm volatile("cp.async.wait_group %0;\n" :: "n"(STAGES - 2));
            __syncthreads();
            if (kt + STAGES - 1 < NKT)
                load_stage(kt + STAGES - 1, (kt + STAGES - 1) & (STAGES - 1));
            asm volatile("cp.async.commit_group;\n" ::);

            const uint32_t as = sb + (kt & (STAGES - 1)) * STAGE_B;
            const uint32_t bs = as + A_TILE_B;

#pragma unroll
            for (int ks = 0; ks < 2; ks++) {
                uint32_t af[4][4];
#pragma unroll
                for (int ms = 0; ms < 4; ms++) {
                    uint32_t row = (uint32_t)(warp_m * 64 + ms * 16) + a_lane_row;
                    ldsm4(af[ms][0], af[ms][1], af[ms][2], af[ms][3],
                          as + row * (RSTRIDE * 2) + ks * 32 + a_lane_k);
                }
                uint32_t bf[4][2];
#pragma unroll
                for (int np = 0; np < 2; np++) {
                    uint32_t row = (uint32_t)(warp_n * 32 + np * 16) + b_lane_row;
                    ldsm4(bf[2 * np][0], bf[2 * np][1], bf[2 * np + 1][0], bf[2 * np + 1][1],
                          bs + row * (RSTRIDE * 2) + ks * 32 + b_lane_k);
                }
#pragma unroll
                for (int ms = 0; ms < 4; ms++)
#pragma unroll
                    for (int nf = 0; nf < 4; nf++)
                        mma_bf16(acc[ms][nf], af[ms], bf[nf]);
            }
        }

        // epilogue: bias + relu -> compact g_h1
#pragma unroll
        for (int ms = 0; ms < 4; ms++) {
            int r0 = m0 + warp_m * 64 + ms * 16 + erow;
#pragma unroll
            for (int nf = 0; nf < 4; nf++) {
                int col = n0 + warp_n * 32 + nf * 8 + ecol;
                if (col < H1) {
                    float2 bb = *(const float2*)(b1 + col);
                    float2 v0, v1;
                    v0.x = fmaxf(acc[ms][nf][0] + bb.x, 0.0f);
                    v0.y = fmaxf(acc[ms][nf][1] + bb.y, 0.0f);
                    v1.x = fmaxf(acc[ms][nf][2] + bb.x, 0.0f);
                    v1.y = fmaxf(acc[ms][nf][3] + bb.y, 0.0f);
                    *(float2*)(g_h1 + (size_t)r0 * H1 + col) = v0;
                    *(float2*)(g_h1 + (size_t)(r0 + 8) * H1 + col) = v1;
                }
            }
        }
        asm volatile("cp.async.wait_group 0;\n" ::);
        __syncthreads();
    }
}

// ============================================================================
// head: GEMM2 k-split partials, combine + GEMM3 + sigmoid (compact rows)
// ============================================================================
__global__ void head_partial_kernel(const float* __restrict__ W2) {
    if (blockIdx.x >= g_mtiles) return;
    __shared__ float hs[128][41];
    __shared__ float w2s[40 * 40];
    const int tid = threadIdx.x;
    const int row0 = blockIdx.x * 128;
    const int kc0 = blockIdx.y * 5;

    float acc[H2];
#pragma unroll
    for (int c = 0; c < H2; c++) acc[c] = 0.0f;

    for (int kc = kc0; kc < kc0 + 5; kc++) {
#pragma unroll 8
        for (int i = 0; i < 40; i++) {
            int idx = tid + 128 * i;
            int r = idx / 40, k = idx - r * 40;
            hs[r][k] = g_h1[(size_t)(row0 + r) * H1 + kc * 40 + k];
        }
#pragma unroll
        for (int i = 0; i < 13; i++) {
            int idx = tid + 128 * i;
            if (idx < 1600) w2s[idx] = W2[kc * 40 * H2 + idx];
        }
        __syncthreads();
#pragma unroll 5
        for (int k = 0; k < 40; k++) {
            float a = hs[tid][k];
            const float4* wr = (const float4*)(w2s + k * H2);
#pragma unroll
            for (int c4 = 0; c4 < 10; c4++) {
                float4 w = wr[c4];
                acc[c4 * 4 + 0] += a * w.x;
                acc[c4 * 4 + 1] += a * w.y;
                acc[c4 * 4 + 2] += a * w.z;
                acc[c4 * 4 + 3] += a * w.w;
            }
        }
        __syncthreads();
    }
    float4* dst = (float4*)&g_part[blockIdx.y][(row0 + tid) * H2];
#pragma unroll
    for (int c4 = 0; c4 < 10; c4++)
        dst[c4] = make_float4(acc[c4 * 4], acc[c4 * 4 + 1], acc[c4 * 4 + 2], acc[c4 * 4 + 3]);
}

__global__ void head_combine_kernel(const float* __restrict__ b2,
                                    const float* __restrict__ W3,
                                    const float* __restrict__ b3) {
    int row = blockIdx.x * blockDim.x + threadIdx.x;
    if (row >= g_mtiles * 128) return;
    float4 a[10];
    const float4* p0 = (const float4*)&g_part[0][row * H2];
#pragma unroll
    for (int i = 0; i < 10; i++) a[i] = p0[i];
#pragma unroll
    for (int p = 1; p < 5; p++) {
        const float4* pp = (const float4*)&g_part[p][row * H2];
#pragma unroll
        for (int i = 0; i < 10; i++) {
            float4 v = pp[i];
            a[i].x += v.x; a[i].y += v.y; a[i].z += v.z; a[i].w += v.w;
        }
    }
    float logit = b3[0];
#pragma unroll
    for (int i = 0; i < 10; i++) {
        float4 bb = *(const float4*)(b2 + i * 4);
        float4 ww = *(const float4*)(W3 + i * 4);
        logit += fmaxf(a[i].x + bb.x, 0.0f) * ww.x;
        logit += fmaxf(a[i].y + bb.y, 0.0f) * ww.y;
        logit += fmaxf(a[i].z + bb.z, 0.0f) * ww.z;
        logit += fmaxf(a[i].w + bb.w, 0.0f) * ww.w;
    }
    g_logits[row] = 1.0f / (1.0f + expf(-logit));
}

// ============================================================================
// masked gather through the inverse map
// ============================================================================
__global__ void gather_kernel(const void* __restrict__ tsp, float* __restrict__ out) {
    int i = blockIdx.x * blockDim.x + threadIdx.x;
    if (i >= MROWS) return;
    long long ts = g_ts_is_i32 ? (long long)((const int*)tsp)[i]
                               : ((const long long*)tsp)[i];
    float r = 0.0f;
    if (ts != 0) {
        int pos = ((i >> 9) << 9) + (int)ts;
        r = g_logits[g_cidx[pos]];
    }
    out[i] = r;
}

// ============================================================================
// launch
// ============================================================================
extern "C" void kernel_launch(void* const* d_in, const int* in_sizes, int n_in,
                              void* d_out, int out_size) {
    const float* X   = (const float*)d_in[0];
    const void*  tsp = d_in[1];
    const float* W1  = (const float*)d_in[2];
    const float* b1  = (const float*)d_in[3];
    const float* W2  = (const float*)d_in[4];
    const float* b2  = (const float*)d_in[5];
    const float* W3  = (const float*)d_in[6];
    const float* b3  = (const float*)d_in[7];
    float* out = (float*)d_out;
    (void)in_sizes; (void)n_in; (void)out_size;

    cudaFuncSetAttribute(gemm1_kernel,
                         cudaFuncAttributeMaxDynamicSharedMemorySize, SMEM_B);

    detect_kernel<<<1, 256>>>((const unsigned int*)tsp);
    zero_mark_kernel<<<1, 1024>>>();
    scatter_mark_kernel<<<8, 1024>>>(tsp);
    scan_kernel<<<1, 1024>>>();

    convert_x_rows_kernel<<<1024, 256>>>(X);
    convert_w1_kernel<<<dim3(KDIM / 32, H1P / 32), dim3(32, 8)>>>(W1);

    gemm1_kernel<<<296, 256, SMEM_B>>>(b1);

    head_partial_kernel<<<dim3(64, 5), 128>>>(W2);
    head_combine_kernel<<<32, 256>>>(b2, W3, b3);
    gather_kernel<<<32, 256>>>(tsp, out);
}

// round 10
// speedup vs baseline: 3.4603x; 1.1835x over previous
#include <cuda_runtime.h>
#include <cuda_bf16.h>
#include <cstdint>
#include <math.h>

// ---------------- problem dims ----------------
#define MROWS 8192
#define KDIM  9984
#define H1    1000
#define H1P   1024
#define H2    40

// ---------------- GEMM1 tiling ----------------
#define BM 128
#define BN 128
#define BK 32
#define STAGES 4
#define NKT (KDIM / BK)          // 312
#define KSPLIT 4
#define KT_PER (NKT / KSPLIT)    // 78
#define RSTRIDE 40               // bf16 elems per smem row (80 B) -> conflict-free ldmatrix
#define A_TILE_B (BM * RSTRIDE * 2)          // 10240
#define STAGE_B  ((BM + BN) * RSTRIDE * 2)   // 20480
#define SMEM_B   (STAGES * STAGE_B)          // 81920

// ---------------- scratch (device globals; no runtime alloc) ----------------
__device__ __nv_bfloat16 g_Xbf[(size_t)MROWS * KDIM];   // compact bf16 X rows
__device__ __nv_bfloat16 g_W1t[(size_t)H1P * KDIM];     // [n][k], rows >= 1000 zero
__device__ float g_psum[(size_t)KSPLIT * MROWS * H1P];  // split-K partials
__device__ float g_h1[(size_t)MROWS * H1];              // compact, post bias+relu
__device__ float g_part[5][MROWS * H2];
__device__ float g_logits[MROWS];                       // compact
__device__ int   g_ts_is_i32;
__device__ unsigned char g_mark[MROWS];
__device__ int   g_cidx[MROWS];                         // (b,s) -> compact row
__device__ int   g_list[MROWS];                         // compact row -> original row
__device__ int   g_count, g_mtiles, g_ntiles, g_tile_ctr;

// ============================================================================
// helpers
// ============================================================================
__device__ __forceinline__ uint32_t smem_u32(const void* p) {
    uint32_t a;
    asm("{ .reg .u64 t; cvta.to.shared.u64 t, %1; cvt.u32.u64 %0, t; }"
        : "=r"(a) : "l"(p));
    return a;
}
__device__ __forceinline__ void cpa16(uint32_t dst, const void* src) {
    asm volatile("cp.async.cg.shared.global [%0], [%1], 16;\n" :: "r"(dst), "l"(src));
}
__device__ __forceinline__ void ldsm4(uint32_t& r0, uint32_t& r1, uint32_t& r2,
                                      uint32_t& r3, uint32_t addr) {
    asm volatile("ldmatrix.sync.aligned.m8n8.x4.shared.b16 {%0,%1,%2,%3}, [%4];"
                 : "=r"(r0), "=r"(r1), "=r"(r2), "=r"(r3) : "r"(addr));
}
__device__ __forceinline__ void mma_bf16(float* d, const uint32_t* a, const uint32_t* b) {
    asm volatile(
        "mma.sync.aligned.m16n8k16.row.col.f32.bf16.bf16.f32 "
        "{%0,%1,%2,%3}, {%4,%5,%6,%7}, {%8,%9}, {%0,%1,%2,%3};\n"
        : "+f"(d[0]), "+f"(d[1]), "+f"(d[2]), "+f"(d[3])
        : "r"(a[0]), "r"(a[1]), "r"(a[2]), "r"(a[3]), "r"(b[0]), "r"(b[1]));
}

// ============================================================================
// pre-chain: zero marks + dtype detect, scatter, scan/compact
// ============================================================================
__global__ void prep_kernel(const unsigned int* __restrict__ w) {
    // block 0: zero marks; block 1: detect dtype
    if (blockIdx.x == 0) {
        ((unsigned long long*)g_mark)[threadIdx.x] = 0ULL;  // 1024 x 8B
    } else {
        __shared__ int s;
        if (threadIdx.x == 0) s = 0;
        __syncthreads();
        int loc = 0;
        for (int i = threadIdx.x; i < 4096; i += 1024)
            if (w[2 * i + 1] != 0u) loc = 1;
        if (loc) s = 1;
        __syncthreads();
        if (threadIdx.x == 0) g_ts_is_i32 = s;
    }
}

__global__ void scatter_mark_kernel(const void* __restrict__ tsp) {
    int i = blockIdx.x * 1024 + threadIdx.x;             // grid 8
    long long ts = g_ts_is_i32 ? (long long)((const int*)tsp)[i]
                               : ((const long long*)tsp)[i];
    if (ts != 0) g_mark[((i >> 9) << 9) + (int)ts] = 1;
}

__global__ void scan_kernel() {
    __shared__ int wsum[32];
    const int tid = threadIdx.x, lane = tid & 31, wid = tid >> 5;
    const int base = tid * 8;
    int loc[8], s = 0;
#pragma unroll
    for (int j = 0; j < 8; j++) { loc[j] = s; s += g_mark[base + j]; }
    int v = s;
#pragma unroll
    for (int o = 1; o < 32; o <<= 1) {
        int u = __shfl_up_sync(0xffffffffu, v, o);
        if (lane >= o) v += u;
    }
    if (lane == 31) wsum[wid] = v;
    __syncthreads();
    if (wid == 0) {
        int w = wsum[lane];
#pragma unroll
        for (int o = 1; o < 32; o <<= 1) {
            int u = __shfl_up_sync(0xffffffffu, w, o);
            if (lane >= o) w += u;
        }
        wsum[lane] = w;
    }
    __syncthreads();
    int tb = (wid > 0 ? wsum[wid - 1] : 0) + (v - s);
#pragma unroll
    for (int j = 0; j < 8; j++) {
        if (g_mark[base + j]) {
            int c = tb + loc[j];
            g_cidx[base + j] = c;
            g_list[c] = base + j;
        }
    }
    int total = wsum[31];
    int mt = (total + 127) >> 7;
    if (tid == 0) {
        g_count = total;
        g_mtiles = mt;
        g_ntiles = mt * (H1P / BN) * KSPLIT;
        g_tile_ctr = 0;
    }
    for (int i = total + tid; i < mt * 128; i += 1024) g_list[i] = 0;  // pad
}

// ============================================================================
// pre-pass: convert only needed X rows fp32 -> bf16 (compact layout)
// ============================================================================
__global__ void convert_x_rows_kernel(const float* __restrict__ X) {
    const int padded = g_mtiles * 128;
    for (int r = blockIdx.x; r < padded; r += gridDim.x) {
        int row = g_list[r];
        const float4* src = (const float4*)(X + (size_t)row * KDIM);
        uint4* dst = (uint4*)(g_Xbf + (size_t)r * KDIM);
        for (int c = threadIdx.x; c < KDIM / 8; c += blockDim.x) {
            float4 v0 = src[2 * c], v1 = src[2 * c + 1];
            __nv_bfloat162 p0 = __floats2bfloat162_rn(v0.x, v0.y);
            __nv_bfloat162 p1 = __floats2bfloat162_rn(v0.z, v0.w);
            __nv_bfloat162 p2 = __floats2bfloat162_rn(v1.x, v1.y);
            __nv_bfloat162 p3 = __floats2bfloat162_rn(v1.z, v1.w);
            uint4 o;
            o.x = *(uint32_t*)&p0; o.y = *(uint32_t*)&p1;
            o.z = *(uint32_t*)&p2; o.w = *(uint32_t*)&p3;
            dst[c] = o;
        }
    }
}

// W1[K][H1] fp32 -> g_W1t[H1P][K] bf16 (transpose + pad)
__global__ void convert_w1_kernel(const float* __restrict__ W1) {
    __shared__ float t[32][33];
    int k0 = blockIdx.x * 32, n0 = blockIdx.y * 32;
#pragma unroll
    for (int yy = 0; yy < 32; yy += 8) {
        int k = k0 + threadIdx.y + yy, n = n0 + threadIdx.x;
        t[threadIdx.y + yy][threadIdx.x] = (n < H1) ? W1[(size_t)k * H1 + n] : 0.0f;
    }
    __syncthreads();
#pragma unroll
    for (int yy = 0; yy < 32; yy += 8) {
        int n = n0 + threadIdx.y + yy, k = k0 + threadIdx.x;
        g_W1t[(size_t)n * KDIM + k] = __float2bfloat16(t[threadIdx.x][threadIdx.y + yy]);
    }
}

// ============================================================================
// GEMM1 (persistent, work-stealing, split-K=4): partials into g_psum
// BM=128 BN=128 BK=32, 8 warps (2m x 4n), warp tile 64x32, 2 CTAs/SM
// unit u: ks = u & 3 (K slice of 78 ktiles), t = u >> 2 -> (m0, n0)
// ============================================================================
__global__ void __launch_bounds__(256, 2)
gemm1_kernel() {
    extern __shared__ __align__(128) char smem[];
    const uint32_t sb = smem_u32(smem);
    __shared__ int s_t;

    const int tid = threadIdx.x;
    const int warp = tid >> 5;
    const int lane = tid & 31;
    const int warp_m = warp & 1;     // 0..1, 64 rows
    const int warp_n = warp >> 1;    // 0..3, 32 cols
    const int ntiles = g_ntiles;

    const int lr = tid >> 2;         // 0..63
    const int lc = tid & 3;          // 0..3
    const uint32_t a_lane_row = (uint32_t)(lane & 15);
    const uint32_t a_lane_k   = (uint32_t)((lane >> 4) * 16);
    const int bj = lane >> 3;
    const uint32_t b_lane_row = (uint32_t)((bj >> 1) * 8 + (lane & 7));
    const uint32_t b_lane_k   = (uint32_t)((bj & 1) * 16);
    const int erow = lane >> 2;
    const int ecol = (lane & 3) * 2;

    while (true) {
        if (tid == 0) s_t = atomicAdd(&g_tile_ctr, 1);
        __syncthreads();
        const int u = s_t;
        if (u >= ntiles) break;
        const int ks = u & (KSPLIT - 1);
        const int t  = u >> 2;
        const int m0 = (t >> 3) * BM;      // H1P/BN = 8 n-tiles
        const int n0 = (t & 7) * BN;

        const __nv_bfloat16* Abase = g_Xbf + (size_t)m0 * KDIM + (size_t)ks * KT_PER * BK;
        const __nv_bfloat16* Bbase = g_W1t + (size_t)n0 * KDIM + (size_t)ks * KT_PER * BK;

        float acc[4][4][4];
#pragma unroll
        for (int i = 0; i < 4; i++)
#pragma unroll
            for (int j = 0; j < 4; j++)
#pragma unroll
                for (int r = 0; r < 4; r++) acc[i][j][r] = 0.0f;

        auto load_stage = [&](int kt, int stage) {
            uint32_t as = sb + stage * STAGE_B;
            uint32_t bs = as + A_TILE_B;
            const __nv_bfloat16* asrc = Abase + (size_t)kt * BK + lc * 8;
            const __nv_bfloat16* bsrc = Bbase + (size_t)kt * BK + lc * 8;
#pragma unroll
            for (int i = 0; i < 2; i++) {
                int r = lr + 64 * i;
                cpa16(as + r * (RSTRIDE * 2) + lc * 16, asrc + (size_t)r * KDIM);
                cpa16(bs + r * (RSTRIDE * 2) + lc * 16, bsrc + (size_t)r * KDIM);
            }
        };

#pragma unroll
        for (int s = 0; s < STAGES - 1; s++) {
            load_stage(s, s);
            asm volatile("cp.async.commit_group;\n" ::);
        }

        for (int kt = 0; kt < KT_PER; kt++) {
            asm volatile("cp.async.wait_group %0;\n" :: "n"(STAGES - 2));
            __syncthreads();
            if (kt + STAGES - 1 < KT_PER)
                load_stage(kt + STAGES - 1, (kt + STAGES - 1) & (STAGES - 1));
            asm volatile("cp.async.commit_group;\n" ::);

            const uint32_t as = sb + (kt & (STAGES - 1)) * STAGE_B;
            const uint32_t bs = as + A_TILE_B;

#pragma unroll
            for (int kss = 0; kss < 2; kss++) {
                uint32_t af[4][4];
#pragma unroll
                for (int ms = 0; ms < 4; ms++) {
                    uint32_t row = (uint32_t)(warp_m * 64 + ms * 16) + a_lane_row;
                    ldsm4(af[ms][0], af[ms][1], af[ms][2], af[ms][3],
                          as + row * (RSTRIDE * 2) + kss * 32 + a_lane_k);
                }
                uint32_t bf[4][2];
#pragma unroll
                for (int np = 0; np < 2; np++) {
                    uint32_t row = (uint32_t)(warp_n * 32 + np * 16) + b_lane_row;
                    ldsm4(bf[2 * np][0], bf[2 * np][1], bf[2 * np + 1][0], bf[2 * np + 1][1],
                          bs + row * (RSTRIDE * 2) + kss * 32 + b_lane_k);
                }
#pragma unroll
                for (int ms = 0; ms < 4; ms++)
#pragma unroll
                    for (int nf = 0; nf < 4; nf++)
                        mma_bf16(acc[ms][nf], af[ms], bf[nf]);
            }
        }

        // epilogue: raw partials -> g_psum[ks] (full 1024-wide, no predicates)
        float* pbase = g_psum + (size_t)ks * MROWS * H1P;
#pragma unroll
        for (int ms = 0; ms < 4; ms++) {
            int r0 = m0 + warp_m * 64 + ms * 16 + erow;
#pragma unroll
            for (int nf = 0; nf < 4; nf++) {
                int col = n0 + warp_n * 32 + nf * 8 + ecol;
                *(float2*)(pbase + (size_t)r0 * H1P + col) =
                    make_float2(acc[ms][nf][0], acc[ms][nf][1]);
                *(float2*)(pbase + (size_t)(r0 + 8) * H1P + col) =
                    make_float2(acc[ms][nf][2], acc[ms][nf][3]);
            }
        }
        asm volatile("cp.async.wait_group 0;\n" ::);
        __syncthreads();
    }
}

// ============================================================================
// combine split-K partials + bias + relu -> g_h1 (cols 0..999 only)
// ============================================================================
__global__ void h1_combine_kernel(const float* __restrict__ b1) {
    const int padded = g_mtiles * 128;
    for (int r = blockIdx.x; r < padded; r += gridDim.x) {
        const float4* p0 = (const float4*)(g_psum + 0 * (size_t)MROWS * H1P + (size_t)r * H1P);
        const float4* p1 = (const float4*)(g_psum + 1 * (size_t)MROWS * H1P + (size_t)r * H1P);
        const float4* p2 = (const float4*)(g_psum + 2 * (size_t)MROWS * H1P + (size_t)r * H1P);
        const float4* p3 = (const float4*)(g_psum + 3 * (size_t)MROWS * H1P + (size_t)r * H1P);
        float4* dst = (float4*)(g_h1 + (size_t)r * H1);
        for (int c = threadIdx.x; c < H1 / 4; c += blockDim.x) {
            float4 a = p0[c], b = p1[c], d = p2[c], e = p3[c];
            float4 bb = *(const float4*)(b1 + 4 * c);
            float4 o;
            o.x = fmaxf(a.x + b.x + d.x + e.x + bb.x, 0.0f);
            o.y = fmaxf(a.y + b.y + d.y + e.y + bb.y, 0.0f);
            o.z = fmaxf(a.z + b.z + d.z + e.z + bb.z, 0.0f);
            o.w = fmaxf(a.w + b.w + d.w + e.w + bb.w, 0.0f);
            dst[c] = o;
        }
    }
}

// ============================================================================
// head: GEMM2 k-split partials, combine + GEMM3 + sigmoid (compact rows)
// ============================================================================
__global__ void head_partial_kernel(const float* __restrict__ W2) {
    if (blockIdx.x >= g_mtiles) return;
    __shared__ float hs[128][41];
    __shared__ float w2s[40 * 40];
    const int tid = threadIdx.x;
    const int row0 = blockIdx.x * 128;
    const int kc0 = blockIdx.y * 5;

    float acc[H2];
#pragma unroll
    for (int c = 0; c < H2; c++) acc[c] = 0.0f;

    for (int kc = kc0; kc < kc0 + 5; kc++) {
#pragma unroll 8
        for (int i = 0; i < 40; i++) {
            int idx = tid + 128 * i;
            int r = idx / 40, k = idx - r * 40;
            hs[r][k] = g_h1[(size_t)(row0 + r) * H1 + kc * 40 + k];
        }
#pragma unroll
        for (int i = 0; i < 13; i++) {
            int idx = tid + 128 * i;
            if (idx < 1600) w2s[idx] = W2[kc * 40 * H2 + idx];
        }
        __syncthreads();
#pragma unroll 5
        for (int k = 0; k < 40; k++) {
            float a = hs[tid][k];
            const float4* wr = (const float4*)(w2s + k * H2);
#pragma unroll
            for (int c4 = 0; c4 < 10; c4++) {
                float4 w = wr[c4];
                acc[c4 * 4 + 0] += a * w.x;
                acc[c4 * 4 + 1] += a * w.y;
                acc[c4 * 4 + 2] += a * w.z;
                acc[c4 * 4 + 3] += a * w.w;
            }
        }
        __syncthreads();
    }
    float4* dst = (float4*)&g_part[blockIdx.y][(row0 + tid) * H2];
#pragma unroll
    for (int c4 = 0; c4 < 10; c4++)
        dst[c4] = make_float4(acc[c4 * 4], acc[c4 * 4 + 1], acc[c4 * 4 + 2], acc[c4 * 4 + 3]);
}

__global__ void head_combine_kernel(const float* __restrict__ b2,
                                    const float* __restrict__ W3,
                                    const float* __restrict__ b3) {
    int row = blockIdx.x * blockDim.x + threadIdx.x;
    if (row >= g_mtiles * 128) return;
    float4 a[10];
    const float4* p0 = (const float4*)&g_part[0][row * H2];
#pragma unroll
    for (int i = 0; i < 10; i++) a[i] = p0[i];
#pragma unroll
    for (int p = 1; p < 5; p++) {
        const float4* pp = (const float4*)&g_part[p][row * H2];
#pragma unroll
        for (int i = 0; i < 10; i++) {
            float4 v = pp[i];
            a[i].x += v.x; a[i].y += v.y; a[i].z += v.z; a[i].w += v.w;
        }
    }
    float logit = b3[0];
#pragma unroll
    for (int i = 0; i < 10; i++) {
        float4 bb = *(const float4*)(b2 + i * 4);
        float4 ww = *(const float4*)(W3 + i * 4);
        logit += fmaxf(a[i].x + bb.x, 0.0f) * ww.x;
        logit += fmaxf(a[i].y + bb.y, 0.0f) * ww.y;
        logit += fmaxf(a[i].z + bb.z, 0.0f) * ww.z;
        logit += fmaxf(a[i].w + bb.w, 0.0f) * ww.w;
    }
    g_logits[row] = 1.0f / (1.0f + expf(-logit));
}

// ============================================================================
// masked gather through the inverse map
// ============================================================================
__global__ void gather_kernel(const void* __restrict__ tsp, float* __restrict__ out) {
    int i = blockIdx.x * blockDim.x + threadIdx.x;
    if (i >= MROWS) return;
    long long ts = g_ts_is_i32 ? (long long)((const int*)tsp)[i]
                               : ((const long long*)tsp)[i];
    float r = 0.0f;
    if (ts != 0) {
        int pos = ((i >> 9) << 9) + (int)ts;
        r = g_logits[g_cidx[pos]];
    }
    out[i] = r;
}

// ============================================================================
// launch
// ============================================================================
extern "C" void kernel_launch(void* const* d_in, const int* in_sizes, int n_in,
                              void* d_out, int out_size) {
    const float* X   = (const float*)d_in[0];
    const void*  tsp = d_in[1];
    const float* W1  = (const float*)d_in[2];
    const float* b1  = (const float*)d_in[3];
    const float* W2  = (const float*)d_in[4];
    const float* b2  = (const float*)d_in[5];
    const float* W3  = (const float*)d_in[6];
    const float* b3  = (const float*)d_in[7];
    float* out = (float*)d_out;
    (void)in_sizes; (void)n_in; (void)out_size;

    cudaFuncSetAttribute(gemm1_kernel,
                         cudaFuncAttributeMaxDynamicSharedMemorySize, SMEM_B);

    prep_kernel<<<2, 1024>>>((const unsigned int*)tsp);
    scatter_mark_kernel<<<8, 1024>>>(tsp);
    scan_kernel<<<1, 1024>>>();

    convert_x_rows_kernel<<<1024, 256>>>(X);
    convert_w1_kernel<<<dim3(KDIM / 32, H1P / 32), dim3(32, 8)>>>(W1);

    gemm1_kernel<<<296, 256, SMEM_B>>>();
    h1_combine_kernel<<<512, 256>>>(b1);

    head_partial_kernel<<<dim3(64, 5), 128>>>(W2);
    head_combine_kernel<<<32, 256>>>(b2, W3, b3);
    gather_kernel<<<32, 256>>>(tsp, out);
}